// round 14
// baseline (speedup 1.0000x reference)
#include <cuda_runtime.h>

#define N0 1024
#define N1 512
#define I0 16
#define I1 64

// scratch (device globals). Zero-invariant is only needed for g_R0/g_R1
// (red4-accumulated; finalize self-zeroes them). Everything else is plainly
// overwritten every launch: no atomics, no cleanup kernel.
__device__ float g_R0[N1 * N0];    // [j][a] : sum over i1 of X[j, i1, a]
__device__ float g_R1[N1 * N0];    // [j][a] : sum over i0 of X[i0, j, a]
__device__ float g_G [N1 * N0];    // [j][a] : X[j, j, a]
__device__ float g_Sp[256 * N0];   // [bx*8+by][a]: per-block partial of S (1 MB)
__device__ float g_Dp[32 * N0];    // [bx][a]: per-i0-group partial of D (diag)
__device__ float g_S [N0];         // sum_j R0[j][a]
__device__ float g_D [N0];         // sum_j X[j,j,a]
__device__ float g_Rh0[N1];        // sum_a R0[j][a]
__device__ float g_Rh1[N1];        // sum_a R1[j][a]
__device__ float g_Gh [N1];        // sum_a X[j,j,a]
__device__ float g_scal[2];        // { sum_a S, sum_a D }

__device__ __forceinline__ void red4(float* addr, float4 v) {
    asm volatile("red.global.add.v4.f32 [%0], {%1, %2, %3, %4};"
                 :: "l"(addr), "f"(v.x), "f"(v.y), "f"(v.z), "f"(v.w)
                 : "memory");
}

__device__ __forceinline__ float warp_sum(float v) {
    #pragma unroll
    for (int o = 16; o > 0; o >>= 1) v += __shfl_down_sync(0xffffffffu, v, o);
    return v;
}

// Single streaming pass over X (1 GiB): 16 i0 x 64 i1 x half-a, 128 threads,
// occ 4 (16 warps/SM — the measured sweet spot). Side traffic: 16 MB (R0)
// + 64 MB (R1) red4 + 1 MB plain Sp stores. No atomics/shfls/fences in the
// heavy blocks (the R10/R11 lesson).
__global__ __launch_bounds__(128, 4) void main_pass(const float* __restrict__ X) {
    const int i0base = blockIdx.x * I0;                 // 32 groups
    const int i1base = blockIdx.y * I1;                 // 8 groups
    const int ax = blockIdx.z * 128 + threadIdx.x;      // float4 lane (0..255)
    const float4* __restrict__ Xv = reinterpret_cast<const float4*>(X);

    // Diagonal gather (one diag block per (bx, z): by == bx % 8), overlapped
    // with the stream. Writes g_G rows and the g_Dp partial for this bx
    // (the two z halves cover disjoint ax ranges of slot bx).
    if ((int)blockIdx.y == (blockIdx.x & 7)) {
        float4 dacc = make_float4(0.f, 0.f, 0.f, 0.f);
        #pragma unroll
        for (int k = 0; k < I0; k++) {
            const int d = i0base + k;
            const float4 v = __ldg(Xv + (size_t)(d * N1 + d) * (N0 / 4) + ax);
            *reinterpret_cast<float4*>(&g_G[(size_t)d * N0 + ax * 4]) = v;
            dacc.x += v.x; dacc.y += v.y; dacc.z += v.z; dacc.w += v.w;
        }
        reinterpret_cast<float4*>(g_Dp)[blockIdx.x * (N0 / 4) + ax] = dacc;
    }

    float4 r0acc[I0];
    #pragma unroll
    for (int k = 0; k < I0; k++) r0acc[k] = make_float4(0.f, 0.f, 0.f, 0.f);

    for (int t = 0; t < I1; t++) {
        const int i1 = i1base + t;
        float4 r1 = make_float4(0.f, 0.f, 0.f, 0.f);
        #pragma unroll
        for (int k = 0; k < I0; k++) {
            const float4 v = __ldcs(Xv + (size_t)((i0base + k) * N1 + i1) * (N0 / 4) + ax);
            r0acc[k].x += v.x; r0acc[k].y += v.y; r0acc[k].z += v.z; r0acc[k].w += v.w;
            r1.x += v.x; r1.y += v.y; r1.z += v.z; r1.w += v.w;
        }
        red4(&g_R1[(size_t)i1 * N0 + ax * 4], r1);
    }

    float4 sacc = make_float4(0.f, 0.f, 0.f, 0.f);
    #pragma unroll
    for (int k = 0; k < I0; k++) {
        red4(&g_R0[(size_t)(i0base + k) * N0 + ax * 4], r0acc[k]);
        sacc.x += r0acc[k].x; sacc.y += r0acc[k].y;
        sacc.z += r0acc[k].z; sacc.w += r0acc[k].w;
    }
    // Per-(bx,by) partial of S: plain store into a dedicated slot — no
    // accumulation, so no zero-invariant needed on g_Sp.
    reinterpret_cast<float4*>(g_Sp)[(blockIdx.x * 8 + blockIdx.y) * (N0 / 4) + ax] = sacc;
}

// smalls: derive every small array from L2-resident scratch. 66 blocks.
//  blocks 0..63 : Rh0/Rh1/Gh row-sums (8 j per block, one j per warp)
//  block 64     : S[a] from the 256 g_Sp partials (+ g_scal[0])
//  block 65     : D[a] from the 32 g_Dp partials (+ g_scal[1])
__global__ __launch_bounds__(256) void smalls() {
    const int b   = blockIdx.x;
    const int tid = threadIdx.x;
    const int wid = tid >> 5;
    const int lane = tid & 31;

    if (b < 64) {
        const int j = b * 8 + wid;   // 512 j total
        float s0 = 0.f, s1 = 0.f, sg = 0.f;
        #pragma unroll
        for (int i = 0; i < 8; i++) {
            const int idx = j * (N0 / 4) + i * 32 + lane;
            const float4 v0 = reinterpret_cast<const float4*>(g_R0)[idx];
            const float4 v1 = reinterpret_cast<const float4*>(g_R1)[idx];
            const float4 vg = reinterpret_cast<const float4*>(g_G )[idx];
            s0 += v0.x + v0.y + v0.z + v0.w;
            s1 += v1.x + v1.y + v1.z + v1.w;
            sg += vg.x + vg.y + vg.z + vg.w;
        }
        s0 = warp_sum(s0); s1 = warp_sum(s1); sg = warp_sum(sg);
        if (lane == 0) { g_Rh0[j] = s0; g_Rh1[j] = s1; g_Gh[j] = sg; }
        return;
    }

    // blocks 64/65: column-reduce a partial array [slots][N0] -> out[N0]
    const float* part = (b == 64) ? g_Sp : g_Dp;
    float*       out  = (b == 64) ? g_S  : g_D;
    const int   nslot = (b == 64) ? 256  : 32;   // Sp: 32 bx x 8 by; Dp: 32 bx
    float tot = 0.f;
    #pragma unroll
    for (int r = 0; r < 4; r++) {
        const int a = tid + r * 256;
        float s = 0.f;
        for (int k = 0; k < nslot; k++) s += part[k * N0 + a];
        out[a] = s;
        tot += s;
    }
    tot = warp_sum(tot);
    __shared__ float sm[8];
    if (lane == 0) sm[wid] = tot;
    __syncthreads();
    if (tid == 0) {
        float a0 = 0.f;
        #pragma unroll
        for (int i = 0; i < 8; i++) a0 += sm[i];
        g_scal[b - 64] = a0;
    }
}

// Transposing finalize: scratch is [j][a], output is Y[a][j].
// 32x32 tiles through smem for coalesced loads AND stores. Each R0/R1
// element is read by exactly one block; the loading thread re-zeros it
// right after the load (race-free), restoring the all-zeros invariant for
// the next kernel_launch call / graph replay.
__global__ void finalize(const float* __restrict__ w, float* __restrict__ Y) {
    __shared__ float t0[32][33], t1[32][33], tg[32][33];
    const int at = blockIdx.x * 32;   // a tile (32 tiles)
    const int jt = blockIdx.y * 32;   // j tile (16 tiles)
    const int tx = threadIdx.x;       // 0..31
    const int ty = threadIdx.y;       // 0..7

    #pragma unroll
    for (int r = 0; r < 4; r++) {
        const int jl = ty + r * 8;
        const size_t base = (size_t)(jt + jl) * N0 + at + tx;
        t0[jl][tx] = g_R0[base];
        t1[jl][tx] = g_R1[base];
        tg[jl][tx] = g_G [base];
        g_R0[base] = 0.f;
        g_R1[base] = 0.f;
    }
    __syncthreads();

    const float w0 = w[0], w1 = w[1], w2 = w[2], w3 = w[3], w4 = w[4];
    const float w5 = w[5], w6 = w[6], w7 = w[7], w8 = w[8], w9 = w[9];
    const float c  = w5 * g_scal[0] + w6 * g_scal[1];
    const int   j  = jt + tx;
    const float cj = c + w7 * g_Rh0[j] + w8 * g_Rh1[j] + w9 * g_Gh[j];

    #pragma unroll
    for (int r = 0; r < 4; r++) {
        const int al = ty + r * 8;
        const int a  = at + al;
        const float val = cj + w0 * g_S[a] + w1 * g_D[a]
                        + w2 * t0[tx][al] + w3 * t1[tx][al] + w4 * tg[tx][al];
        Y[(size_t)a * N1 + j] = val;
    }
}

extern "C" void kernel_launch(void* const* d_in, const int* in_sizes, int n_in,
                              void* d_out, int out_size) {
    const float* X = (const float*)d_in[0];   // (512, 512, 1024) fp32
    const float* w = (const float*)d_in[1];   // (10, 1, 1) fp32
    float* Y = (float*)d_out;                 // (1024, 512) fp32

    main_pass<<<dim3(N1 / I0, N1 / I1, 2), 128>>>(X);
    smalls<<<66, 256>>>();
    finalize<<<dim3(N0 / 32, N1 / 32), dim3(32, 8)>>>(w, Y);
}

// round 15
// speedup vs baseline: 1.1640x; 1.1640x over previous
#include <cuda_runtime.h>

#define N0 1024
#define N1 512
#define I0 16
#define I1 64

// scratch (device globals). Zero-invariant is only needed for g_R0/g_R1
// (red4-accumulated; finalize self-zeroes them). Everything else is plainly
// overwritten every launch: no atomics on small arrays, no cleanup kernel.
__device__ float g_R0[N1 * N0];    // [j][a] : sum over i1 of X[j, i1, a]
__device__ float g_R1[N1 * N0];    // [j][a] : sum over i0 of X[i0, j, a]
__device__ float g_G [N1 * N0];    // [j][a] : X[j, j, a]
__device__ float g_Sp[256 * N0];   // [bx*8+by][a]: per-block partial of S (1 MB)
__device__ float g_Dp[32 * N0];    // [bx][a]: per-i0-group partial of D (diag)
__device__ float g_S [N0];         // sum_j R0[j][a]
__device__ float g_D [N0];         // sum_j X[j,j,a]
__device__ float g_Rh0[N1];        // sum_a R0[j][a]
__device__ float g_Rh1[N1];        // sum_a R1[j][a]
__device__ float g_Gh [N1];        // sum_a X[j,j,a]

__device__ __forceinline__ void red4(float* addr, float4 v) {
    asm volatile("red.global.add.v4.f32 [%0], {%1, %2, %3, %4};"
                 :: "l"(addr), "f"(v.x), "f"(v.y), "f"(v.z), "f"(v.w)
                 : "memory");
}

__device__ __forceinline__ float warp_sum(float v) {
    #pragma unroll
    for (int o = 16; o > 0; o >>= 1) v += __shfl_down_sync(0xffffffffu, v, o);
    return v;
}

// Single streaming pass over X (1 GiB): 16 i0 x 64 i1 x half-a, 128 threads,
// occ 4 (16 warps/SM — measured sweet spot). Side traffic: 16 MB (R0) +
// 64 MB (R1) red4 + 1 MB plain Sp stores. No atomics/shfls/fences in the
// heavy blocks.
__global__ __launch_bounds__(128, 4) void main_pass(const float* __restrict__ X) {
    const int i0base = blockIdx.x * I0;                 // 32 groups
    const int i1base = blockIdx.y * I1;                 // 8 groups
    const int ax = blockIdx.z * 128 + threadIdx.x;      // float4 lane (0..255)
    const float4* __restrict__ Xv = reinterpret_cast<const float4*>(X);

    // Diagonal gather (one diag block per (bx, z): by == bx % 8), overlapped
    // with the stream. Writes g_G rows and the g_Dp partial for this bx
    // (the two z halves cover disjoint ax ranges of slot bx).
    if ((int)blockIdx.y == (blockIdx.x & 7)) {
        float4 dacc = make_float4(0.f, 0.f, 0.f, 0.f);
        #pragma unroll
        for (int k = 0; k < I0; k++) {
            const int d = i0base + k;
            const float4 v = __ldg(Xv + (size_t)(d * N1 + d) * (N0 / 4) + ax);
            *reinterpret_cast<float4*>(&g_G[(size_t)d * N0 + ax * 4]) = v;
            dacc.x += v.x; dacc.y += v.y; dacc.z += v.z; dacc.w += v.w;
        }
        reinterpret_cast<float4*>(g_Dp)[blockIdx.x * (N0 / 4) + ax] = dacc;
    }

    float4 r0acc[I0];
    #pragma unroll
    for (int k = 0; k < I0; k++) r0acc[k] = make_float4(0.f, 0.f, 0.f, 0.f);

    for (int t = 0; t < I1; t++) {
        const int i1 = i1base + t;
        float4 r1 = make_float4(0.f, 0.f, 0.f, 0.f);
        #pragma unroll
        for (int k = 0; k < I0; k++) {
            const float4 v = __ldcs(Xv + (size_t)((i0base + k) * N1 + i1) * (N0 / 4) + ax);
            r0acc[k].x += v.x; r0acc[k].y += v.y; r0acc[k].z += v.z; r0acc[k].w += v.w;
            r1.x += v.x; r1.y += v.y; r1.z += v.z; r1.w += v.w;
        }
        red4(&g_R1[(size_t)i1 * N0 + ax * 4], r1);
    }

    float4 sacc = make_float4(0.f, 0.f, 0.f, 0.f);
    #pragma unroll
    for (int k = 0; k < I0; k++) {
        red4(&g_R0[(size_t)(i0base + k) * N0 + ax * 4], r0acc[k]);
        sacc.x += r0acc[k].x; sacc.y += r0acc[k].y;
        sacc.z += r0acc[k].z; sacc.w += r0acc[k].w;
    }
    // Per-(bx,by) partial of S: plain store into a dedicated slot.
    reinterpret_cast<float4*>(g_Sp)[(blockIdx.x * 8 + blockIdx.y) * (N0 / 4) + ax] = sacc;
}

// smalls: derive the small arrays from L2-resident scratch. 76 blocks, all
// loop bounds compile-time (the R14 failure was a runtime-bound loop the
// compiler couldn't unroll -> serialized L2 latency chain).
//  blocks 0..63 : Rh0/Rh1/Gh row-sums (8 j per block, one j per warp)
//  blocks 64..71: S[a] — each block 128 a, 2 threads/a over 256 Sp slots
//  blocks 72..75: D[a] — each block 256 a, 32 Dp slots per thread
__global__ __launch_bounds__(256) void smalls() {
    const int b   = blockIdx.x;
    const int tid = threadIdx.x;
    const int wid = tid >> 5;
    const int lane = tid & 31;

    if (b < 64) {
        const int j = b * 8 + wid;   // 512 j total
        float s0 = 0.f, s1 = 0.f, sg = 0.f;
        #pragma unroll
        for (int i = 0; i < 8; i++) {
            const int idx = j * (N0 / 4) + i * 32 + lane;
            const float4 v0 = reinterpret_cast<const float4*>(g_R0)[idx];
            const float4 v1 = reinterpret_cast<const float4*>(g_R1)[idx];
            const float4 vg = reinterpret_cast<const float4*>(g_G )[idx];
            s0 += v0.x + v0.y + v0.z + v0.w;
            s1 += v1.x + v1.y + v1.z + v1.w;
            sg += vg.x + vg.y + vg.z + vg.w;
        }
        s0 = warp_sum(s0); s1 = warp_sum(s1); sg = warp_sum(sg);
        if (lane == 0) { g_Rh0[j] = s0; g_Rh1[j] = s1; g_Gh[j] = sg; }
        return;
    }

    if (b < 72) {
        // S: 256 slots x 1024 a. Block covers 128 a; threads split slots 2-way.
        const int a    = (b - 64) * 128 + (tid & 127);
        const int half = tid >> 7;                       // 0 or 1
        const float* p = g_Sp + half * 128 * N0 + a;
        float s = 0.f;
        #pragma unroll 8
        for (int k = 0; k < 128; k++) s += p[k * N0];
        __shared__ float sh[128];
        if (half) sh[tid - 128] = s;
        __syncthreads();
        if (!half) g_S[a] = s + sh[tid];
        return;
    }

    // D: 32 slots x 1024 a. Block covers 256 a; one thread per a.
    {
        const int a = (b - 72) * 256 + tid;
        float s = 0.f;
        #pragma unroll
        for (int k = 0; k < 32; k++) s += g_Dp[k * N0 + a];
        g_D[a] = s;
    }
}

// Transposing finalize: scratch is [j][a], output is Y[a][j].
// 32x32 tiles through smem for coalesced loads AND stores. Each R0/R1
// element is read by exactly one block; the loading thread re-zeros it
// right after the load (race-free), restoring the zero invariant.
// The two global scalars (sum_a S = sum_j Rh0, sum_a D = sum_j Gh) are
// computed block-locally from the 512-float L2-hot Rh0/Gh arrays,
// overlapped with the tile loads — no g_scal global, no extra kernel.
__global__ void finalize(const float* __restrict__ w, float* __restrict__ Y) {
    __shared__ float t0[32][33], t1[32][33], tg[32][33];
    __shared__ float sred[2][8];
    const int at = blockIdx.x * 32;   // a tile (32 tiles)
    const int jt = blockIdx.y * 32;   // j tile (16 tiles)
    const int tx = threadIdx.x;       // 0..31
    const int ty = threadIdx.y;       // 0..7
    const int tid = ty * 32 + tx;     // 0..255
    const int lane = tid & 31, wd = tid >> 5;

    // scalar partials (overlap with tile loads below)
    float sc0 = g_Rh0[tid] + g_Rh0[tid + 256];
    float scg = g_Gh [tid] + g_Gh [tid + 256];

    #pragma unroll
    for (int r = 0; r < 4; r++) {
        const int jl = ty + r * 8;
        const size_t base = (size_t)(jt + jl) * N0 + at + tx;
        t0[jl][tx] = g_R0[base];
        t1[jl][tx] = g_R1[base];
        tg[jl][tx] = g_G [base];
        g_R0[base] = 0.f;
        g_R1[base] = 0.f;
    }

    sc0 = warp_sum(sc0);
    scg = warp_sum(scg);
    if (lane == 0) { sred[0][wd] = sc0; sred[1][wd] = scg; }
    __syncthreads();

    float scal0 = 0.f, scal1 = 0.f;
    #pragma unroll
    for (int i = 0; i < 8; i++) { scal0 += sred[0][i]; scal1 += sred[1][i]; }

    const float w0 = w[0], w1 = w[1], w2 = w[2], w3 = w[3], w4 = w[4];
    const float w5 = w[5], w6 = w[6], w7 = w[7], w8 = w[8], w9 = w[9];
    const float c  = w5 * scal0 + w6 * scal1;
    const int   j  = jt + tx;
    const float cj = c + w7 * g_Rh0[j] + w8 * g_Rh1[j] + w9 * g_Gh[j];

    #pragma unroll
    for (int r = 0; r < 4; r++) {
        const int al = ty + r * 8;
        const int a  = at + al;
        const float val = cj + w0 * g_S[a] + w1 * g_D[a]
                        + w2 * t0[tx][al] + w3 * t1[tx][al] + w4 * tg[tx][al];
        Y[(size_t)a * N1 + j] = val;
    }
}

extern "C" void kernel_launch(void* const* d_in, const int* in_sizes, int n_in,
                              void* d_out, int out_size) {
    const float* X = (const float*)d_in[0];   // (512, 512, 1024) fp32
    const float* w = (const float*)d_in[1];   // (10, 1, 1) fp32
    float* Y = (float*)d_out;                 // (1024, 512) fp32

    main_pass<<<dim3(N1 / I0, N1 / I1, 2), 128>>>(X);
    smalls<<<76, 256>>>();
    finalize<<<dim3(N0 / 32, N1 / 32), dim3(32, 8)>>>(w, Y);
}

// round 16
// speedup vs baseline: 1.1763x; 1.0106x over previous
#include <cuda_runtime.h>

#define N0 1024
#define N1 512
#define I0 32
#define I1 64

// scratch (device globals). Zero-invariant only on g_R0/g_R1 (red-accumulated;
// finalize self-zeroes them). Everything else plainly overwritten each launch.
__device__ float g_R0[N1 * N0];    // [j][a] : sum over i1 of X[j, i1, a]
__device__ float g_R1[N1 * N0];    // [j][a] : sum over i0 of X[i0, j, a]
__device__ float g_G [N1 * N0];    // [j][a] : X[j, j, a]
__device__ float g_Sp[128 * N0];   // [bx*8+by][a]: per-block partial of S (512 KB)
__device__ float g_Dp[16 * N0];    // [bx][a]: per-i0-group partial of D (64 KB)
__device__ float g_S [N0];         // sum_j R0[j][a]
__device__ float g_D [N0];         // sum_j X[j,j,a]
__device__ float g_Rh0[N1];        // sum_a R0[j][a]
__device__ float g_Rh1[N1];        // sum_a R1[j][a]
__device__ float g_Gh [N1];        // sum_a X[j,j,a]

__device__ __forceinline__ void red2(float* addr, float2 v) {
    asm volatile("red.global.add.v2.f32 [%0], {%1, %2};"
                 :: "l"(addr), "f"(v.x), "f"(v.y) : "memory");
}

__device__ __forceinline__ float warp_sum(float v) {
    #pragma unroll
    for (int o = 16; o > 0; o >>= 1) v += __shfl_down_sync(0xffffffffu, v, o);
    return v;
}

// Single streaming pass over X (1 GiB). NEW geometry: float2 lanes so that
// I0=32 fits at 16 warps/SM (the measured sweet spot): 256 threads x float2
// = half-row, r0acc = 32 x float2 = 64 regs -> ~100 total -> occ 2 = 16
// warps. Side-atomic traffic drops 81 -> 49 MB (R1 32 MB, R0 16 MB, Sp 1),
// the variable with measured slope ~0.18us/MB. Grid (16 bx, 8 by, 2 z),
// 512 blocks of 2 MB. No atomics/shfls/fences beyond the red2 partials.
__global__ __launch_bounds__(256, 2) void main_pass(const float* __restrict__ X) {
    const int i0base = blockIdx.x * I0;                 // 16 groups
    const int i1base = blockIdx.y * I1;                 // 8 groups
    const int aq = blockIdx.z * 256 + threadIdx.x;      // float2 lane (0..511)
    const float2* __restrict__ Xv = reinterpret_cast<const float2*>(X);

    // Diagonal gather (one diag block per (bx, z): by == bx & 7), overlapped
    // with the stream. Writes g_G rows and the g_Dp partial for this bx
    // (the two z halves cover disjoint aq ranges of slot bx).
    if ((int)blockIdx.y == (int)(blockIdx.x & 7)) {
        float2 dacc = make_float2(0.f, 0.f);
        #pragma unroll
        for (int k = 0; k < I0; k++) {
            const int d = i0base + k;
            const float2 v = __ldg(Xv + (size_t)(d * N1 + d) * (N0 / 2) + aq);
            reinterpret_cast<float2*>(g_G)[(size_t)d * (N0 / 2) + aq] = v;
            dacc.x += v.x; dacc.y += v.y;
        }
        reinterpret_cast<float2*>(g_Dp)[blockIdx.x * (N0 / 2) + aq] = dacc;
    }

    float2 r0acc[I0];
    #pragma unroll
    for (int k = 0; k < I0; k++) r0acc[k] = make_float2(0.f, 0.f);

    for (int t = 0; t < I1; t++) {
        const int i1 = i1base + t;
        float2 r1 = make_float2(0.f, 0.f);
        #pragma unroll
        for (int k = 0; k < I0; k++) {
            const float2 v = __ldcs(Xv + (size_t)((i0base + k) * N1 + i1) * (N0 / 2) + aq);
            r0acc[k].x += v.x; r0acc[k].y += v.y;
            r1.x += v.x; r1.y += v.y;
        }
        red2(&g_R1[(size_t)i1 * N0 + aq * 2], r1);
    }

    float2 sacc = make_float2(0.f, 0.f);
    #pragma unroll
    for (int k = 0; k < I0; k++) {
        red2(&g_R0[(size_t)(i0base + k) * N0 + aq * 2], r0acc[k]);
        sacc.x += r0acc[k].x; sacc.y += r0acc[k].y;
    }
    // Per-(bx,by) partial of S: plain store into a dedicated slot.
    reinterpret_cast<float2*>(g_Sp)[(blockIdx.x * 8 + blockIdx.y) * (N0 / 2) + aq] = sacc;
}

// smalls: 64 balanced blocks, all compile-time loop bounds.
//  - rowsums: j = b*8 + wid, one j per warp (Rh0/Rh1/Gh)
//  - S: block b covers a in [b*16, b*16+16): 16 slot-groups of 8, smem-combined
//  - D: 16 threads sum the 16 Dp slots for the same 16 a's
__global__ __launch_bounds__(256) void smalls() {
    const int b   = blockIdx.x;
    const int tid = threadIdx.x;
    const int wid = tid >> 5;
    const int lane = tid & 31;

    // rowsums (6 MB of L2 reads spread over all 64 blocks)
    {
        const int j = b * 8 + wid;   // 512 j total
        float s0 = 0.f, s1 = 0.f, sg = 0.f;
        #pragma unroll
        for (int i = 0; i < 8; i++) {
            const int idx = j * (N0 / 4) + i * 32 + lane;
            const float4 v0 = reinterpret_cast<const float4*>(g_R0)[idx];
            const float4 v1 = reinterpret_cast<const float4*>(g_R1)[idx];
            const float4 vg = reinterpret_cast<const float4*>(g_G )[idx];
            s0 += v0.x + v0.y + v0.z + v0.w;
            s1 += v1.x + v1.y + v1.z + v1.w;
            sg += vg.x + vg.y + vg.z + vg.w;
        }
        s0 = warp_sum(s0); s1 = warp_sum(s1); sg = warp_sum(sg);
        if (lane == 0) { g_Rh0[j] = s0; g_Rh1[j] = s1; g_Gh[j] = sg; }
    }

    // S: 128 slots x 16 a per block
    __shared__ float sh[16][17];
    const int al = tid & 15;          // a within block range
    const int sg2 = tid >> 4;         // slot group 0..15
    const int a  = b * 16 + al;
    float s = 0.f;
    #pragma unroll
    for (int i = 0; i < 8; i++) s += g_Sp[(sg2 * 8 + i) * N0 + a];
    sh[sg2][al] = s;
    __syncthreads();
    if (tid < 16) {
        const int aa = b * 16 + tid;
        float ssum = 0.f;
        #pragma unroll
        for (int k = 0; k < 16; k++) ssum += sh[k][tid];
        g_S[aa] = ssum;
        float d = 0.f;
        #pragma unroll
        for (int k = 0; k < 16; k++) d += g_Dp[k * N0 + aa];
        g_D[aa] = d;
    }
}

// Transposing finalize: scratch is [j][a], output is Y[a][j].
// 32x32 tiles through smem for coalesced loads AND stores. Each R0/R1
// element is read by exactly one block; the loading thread re-zeros it
// right after the load (race-free), restoring the zero invariant.
// The two global scalars (sum_a S = sum_j Rh0, sum_a D = sum_j Gh) are
// computed block-locally from the L2-hot 512-float Rh0/Gh arrays,
// overlapped with the tile loads.
__global__ void finalize(const float* __restrict__ w, float* __restrict__ Y) {
    __shared__ float t0[32][33], t1[32][33], tg[32][33];
    __shared__ float sred[2][8];
    const int at = blockIdx.x * 32;   // a tile (32 tiles)
    const int jt = blockIdx.y * 32;   // j tile (16 tiles)
    const int tx = threadIdx.x;       // 0..31
    const int ty = threadIdx.y;       // 0..7
    const int tid = ty * 32 + tx;     // 0..255
    const int lane = tid & 31, wd = tid >> 5;

    // scalar partials (overlap with tile loads below)
    float sc0 = g_Rh0[tid] + g_Rh0[tid + 256];
    float scg = g_Gh [tid] + g_Gh [tid + 256];

    #pragma unroll
    for (int r = 0; r < 4; r++) {
        const int jl = ty + r * 8;
        const size_t base = (size_t)(jt + jl) * N0 + at + tx;
        t0[jl][tx] = g_R0[base];
        t1[jl][tx] = g_R1[base];
        tg[jl][tx] = g_G [base];
        g_R0[base] = 0.f;
        g_R1[base] = 0.f;
    }

    sc0 = warp_sum(sc0);
    scg = warp_sum(scg);
    if (lane == 0) { sred[0][wd] = sc0; sred[1][wd] = scg; }
    __syncthreads();

    float scal0 = 0.f, scal1 = 0.f;
    #pragma unroll
    for (int i = 0; i < 8; i++) { scal0 += sred[0][i]; scal1 += sred[1][i]; }

    const float w0 = w[0], w1 = w[1], w2 = w[2], w3 = w[3], w4 = w[4];
    const float w5 = w[5], w6 = w[6], w7 = w[7], w8 = w[8], w9 = w[9];
    const float c  = w5 * scal0 + w6 * scal1;
    const int   j  = jt + tx;
    const float cj = c + w7 * g_Rh0[j] + w8 * g_Rh1[j] + w9 * g_Gh[j];

    #pragma unroll
    for (int r = 0; r < 4; r++) {
        const int al = ty + r * 8;
        const int a  = at + al;
        const float val = cj + w0 * g_S[a] + w1 * g_D[a]
                        + w2 * t0[tx][al] + w3 * t1[tx][al] + w4 * tg[tx][al];
        Y[(size_t)a * N1 + j] = val;
    }
}

extern "C" void kernel_launch(void* const* d_in, const int* in_sizes, int n_in,
                              void* d_out, int out_size) {
    const float* X = (const float*)d_in[0];   // (512, 512, 1024) fp32
    const float* w = (const float*)d_in[1];   // (10, 1, 1) fp32
    float* Y = (float*)d_out;                 // (1024, 512) fp32

    main_pass<<<dim3(N1 / I0, N1 / I1, 2), 256>>>(X);
    smalls<<<64, 256>>>();
    finalize<<<dim3(N0 / 32, N1 / 32), dim3(32, 8)>>>(w, Y);
}

// round 17
// speedup vs baseline: 1.1784x; 1.0018x over previous
#include <cuda_runtime.h>

#define N0 1024
#define N1 512
#define I0 16
#define I1 64

// scratch (device globals). g_R0/g_R1 zero-invariant maintained by finalize
// (self-zero after read); g_S/g_D/g_scal zeroed by main block (0,0,z);
// g_G and the small outputs plainly overwritten each launch.
__device__ float g_R0[N1 * N0];   // [j][a] : sum over i1 of X[j, i1, a]
__device__ float g_R1[N1 * N0];   // [j][a] : sum over i0 of X[i0, j, a]
__device__ float g_G [N1 * N0];   // [j][a] : X[j, j, a]
__device__ float g_S [N0];        // sum_j R0[j][a]
__device__ float g_D [N0];        // sum_j X[j,j,a]
__device__ float g_Rh0[N1];       // sum_a R0[j][a]
__device__ float g_Rh1[N1];       // sum_a R1[j][a]
__device__ float g_Gh [N1];       // sum_a X[j,j,a]
__device__ float g_scal[2];       // { sum_a S, sum_a D }

__device__ __forceinline__ void red4(float* addr, float4 v) {
    asm volatile("red.global.add.v4.f32 [%0], {%1, %2, %3, %4};"
                 :: "l"(addr), "f"(v.x), "f"(v.y), "f"(v.z), "f"(v.w)
                 : "memory");
}

// Single streaming pass over X (1 GiB) — R5-exact, the best measured main
// (162.7us): 16 i0 x 64 i1 x half-a, 128 threads, occ 4 (16 warps/SM),
// 512 blocks. Side traffic 16 MB (R0) + 64 MB (R1) red4, all L2-resident.
// Blocks (0,0,z) zero the small scratch for reduce_j.
__global__ __launch_bounds__(128, 4) void main_pass(const float* __restrict__ X) {
    const int i0base = blockIdx.x * I0;                 // 32 groups
    const int i1base = blockIdx.y * I1;                 // 8 groups
    const int ax = blockIdx.z * 128 + threadIdx.x;      // float4 lane (0..255)
    const float4* __restrict__ Xv = reinterpret_cast<const float4*>(X);

    if (blockIdx.x == 0 && blockIdx.y == 0) {
        const float4 z = make_float4(0.f, 0.f, 0.f, 0.f);
        reinterpret_cast<float4*>(g_S)[ax] = z;
        reinterpret_cast<float4*>(g_D)[ax] = z;
        if (ax == 0) { g_scal[0] = 0.f; g_scal[1] = 0.f; }
    }

    float4 r0acc[I0];
    #pragma unroll
    for (int k = 0; k < I0; k++) r0acc[k] = make_float4(0.f, 0.f, 0.f, 0.f);

    for (int t = 0; t < I1; t++) {
        const int i1 = i1base + t;
        float4 r1 = make_float4(0.f, 0.f, 0.f, 0.f);
        #pragma unroll
        for (int k = 0; k < I0; k++) {
            const float4 v = __ldcs(Xv + (size_t)((i0base + k) * N1 + i1) * (N0 / 4) + ax);
            r0acc[k].x += v.x; r0acc[k].y += v.y; r0acc[k].z += v.z; r0acc[k].w += v.w;
            r1.x += v.x; r1.y += v.y; r1.z += v.z; r1.w += v.w;
        }
        red4(&g_R1[(size_t)i1 * N0 + ax * 4], r1);
    }
    #pragma unroll
    for (int k = 0; k < I0; k++)
        red4(&g_R0[(size_t)(i0base + k) * N0 + ax * 4], r0acc[k]);
}

// Per-j reductions over a, diagonal gather into g_G, S[a]/D[a] scatter, and
// the global scalars — R6-exact (best measured tail).
__global__ void reduce_j(const float* __restrict__ X) {
    const int j  = blockIdx.x;    // 0..511
    const int tx = threadIdx.x;   // 0..255 (float4 lanes over a)

    const float4 r0 = reinterpret_cast<const float4*>(g_R0)[j * (N0 / 4) + tx];
    const float4 r1 = reinterpret_cast<const float4*>(g_R1)[j * (N0 / 4) + tx];
    const float4 g  = __ldg(reinterpret_cast<const float4*>(X) +
                            (size_t)(j * N1 + j) * (N0 / 4) + tx);
    reinterpret_cast<float4*>(g_G)[j * (N0 / 4) + tx] = g;

    red4(&g_S[tx * 4], r0);
    red4(&g_D[tx * 4], g);

    float s0 = r0.x + r0.y + r0.z + r0.w;
    float s1 = r1.x + r1.y + r1.z + r1.w;
    float sg = g.x  + g.y  + g.z  + g.w;

    #pragma unroll
    for (int o = 16; o > 0; o >>= 1) {
        s0 += __shfl_down_sync(0xffffffffu, s0, o);
        s1 += __shfl_down_sync(0xffffffffu, s1, o);
        sg += __shfl_down_sync(0xffffffffu, sg, o);
    }
    __shared__ float sm[3][8];
    const int lane = tx & 31, w = tx >> 5;
    if (lane == 0) { sm[0][w] = s0; sm[1][w] = s1; sm[2][w] = sg; }
    __syncthreads();
    if (tx == 0) {
        float a0 = 0.f, a1 = 0.f, ag = 0.f;
        #pragma unroll
        for (int i = 0; i < 8; i++) { a0 += sm[0][i]; a1 += sm[1][i]; ag += sm[2][i]; }
        g_Rh0[j] = a0; g_Rh1[j] = a1; g_Gh[j] = ag;
        atomicAdd(&g_scal[0], a0);   // sum_a S
        atomicAdd(&g_scal[1], ag);   // sum_a D
    }
}

// Transposing finalize, REBUILT: 64j x 64a tiles -> 128 blocks (single wave,
// ~4x less launch/ramp overhead than the 512-block version). Three 64x64
// tiles = exactly 48 KB smem using XOR swizzle (al ^ (jl & 31)) instead of
// padding: store phase (jl fixed, al consecutive) and transposed read phase
// (al fixed, jl consecutive) are both bank-conflict-free.
// Each R0/R1 element is read by exactly one block; the loading thread
// re-zeros it (race-free), restoring the zero invariant for the next replay.
#define SWZ(jl, al) ((al) ^ ((jl) & 31))
__global__ __launch_bounds__(256) void finalize(const float* __restrict__ w,
                                                float* __restrict__ Y) {
    __shared__ float t0[64][64], t1[64][64], tg[64][64];
    const int at = blockIdx.x * 64;   // 16 tiles over a
    const int jt = blockIdx.y * 64;   // 8 tiles over j
    const int tid = threadIdx.x;      // 0..255

    #pragma unroll
    for (int r = 0; r < 16; r++) {
        const int idx = r * 256 + tid;      // 0..4095
        const int jl = idx >> 6;            // 0..63
        const int al = idx & 63;            // 0..63
        const size_t base = (size_t)(jt + jl) * N0 + at + al;
        t0[jl][SWZ(jl, al)] = g_R0[base];
        t1[jl][SWZ(jl, al)] = g_R1[base];
        tg[jl][SWZ(jl, al)] = g_G [base];
        g_R0[base] = 0.f;
        g_R1[base] = 0.f;
    }
    __syncthreads();

    const float w0 = w[0], w1 = w[1], w2 = w[2], w3 = w[3], w4 = w[4];
    const float w5 = w[5], w6 = w[6], w7 = w[7], w8 = w[8], w9 = w[9];
    const float c  = w5 * g_scal[0] + w6 * g_scal[1];

    #pragma unroll
    for (int r = 0; r < 16; r++) {
        const int idx = r * 256 + tid;      // 0..4095
        const int al = idx >> 6;            // 0..63 (a within tile, fixed/warp)
        const int jl = idx & 63;            // 0..63 (j consecutive within warp)
        const int a  = at + al;
        const int j  = jt + jl;
        const float val = c
            + w0 * g_S[a] + w1 * g_D[a]
            + w7 * g_Rh0[j] + w8 * g_Rh1[j] + w9 * g_Gh[j]
            + w2 * t0[jl][SWZ(jl, al)]
            + w3 * t1[jl][SWZ(jl, al)]
            + w4 * tg[jl][SWZ(jl, al)];
        Y[(size_t)a * N1 + j] = val;
    }
}

extern "C" void kernel_launch(void* const* d_in, const int* in_sizes, int n_in,
                              void* d_out, int out_size) {
    const float* X = (const float*)d_in[0];   // (512, 512, 1024) fp32
    const float* w = (const float*)d_in[1];   // (10, 1, 1) fp32
    float* Y = (float*)d_out;                 // (1024, 512) fp32

    main_pass<<<dim3(N1 / I0, N1 / I1, 2), 128>>>(X);
    reduce_j<<<N1, 256>>>(X);
    finalize<<<dim3(N0 / 64, N1 / 64), 256>>>(w, Y);
}